// round 8
// baseline (speedup 1.0000x reference)
#include <cuda_runtime.h>
#include <cstdint>

#define VOCAB 32000
#define EMB   256
#define HID   512
#define NOUT  5
#define SEQ   512
#define BATCH 64
#define G3    1536   // 3*HID

// ---------------- scratch (static device allocations only) ----------------
__device__ float g_xg[(size_t)SEQ * BATCH * G3];   // 201 MB: precomputed input gates
__device__ float g_h[2][BATCH * HID];              // double-buffered hidden state
__device__ float g_hfinal[BATCH * HID];            // final hidden per batch
__device__ int            g_bar_cnt[8];            // per-group arrival counter (monotonic)
__device__ volatile int   g_bar_epoch[8];          // per-group release epoch

// ---------------- packed fp32x2 FMA (Blackwell; 2x FFMA throughput) -------
__device__ __forceinline__ void ffma2(unsigned long long& acc,
                                      unsigned long long a,
                                      unsigned long long b) {
    asm("fma.rn.f32x2 %0, %1, %2, %0;" : "+l"(acc) : "l"(a), "l"(b));
}
__device__ __forceinline__ float hsum2(unsigned long long v) {
    float lo = __uint_as_float((unsigned)(v & 0xffffffffull));
    float hi = __uint_as_float((unsigned)(v >> 32));
    return lo + hi;
}

// ---------------- init: zero h0 + barrier state (every launch) ------------
__global__ void k_init() {
    int i = blockIdx.x * blockDim.x + threadIdx.x;
    if (i < BATCH * HID) g_h[0][i] = 0.0f;
    if (i < 8) { g_bar_cnt[i] = 0; g_bar_epoch[i] = 0; }
}

// ---------------- phase 1: x_gates = emb[seq] @ w_ih^T + b_ih -------------
// grid (64 batch, 8 s-tiles of 64, 12 n-chunks of 128), 256 threads.
// SMEM: x tile [64][260] floats (k-pairs contiguous, padded pitch),
//       w tile transposed k-pair-major [128 kp][129 float2].
#define P1_SMEM ((64 * 260 + 128 * 258) * 4)
__global__ void __launch_bounds__(256, 1)
k_xgates(const int* __restrict__ seq, const int* __restrict__ lengths,
         const float* __restrict__ emb, const float* __restrict__ w_ih,
         const float* __restrict__ b_ih) {
    const int b = blockIdx.x, st = blockIdx.y, nc = blockIdx.z;
    const int s0 = st * 64, n0 = nc * 128;
    if (s0 >= lengths[b]) return;  // dead steps never read downstream

    extern __shared__ float sm1[];
    float* xs = sm1;               // [64][260]
    float* ws = sm1 + 64 * 260;    // [128][258] = [kp][129 float2]
    const int tid = threadIdx.x;

    // gather 64 embedding rows (one s-tile, fixed batch)
    {
        int r = tid >> 2, part = tid & 3;
        int tok = seq[(s0 + r) * BATCH + b];
        const float4* src = reinterpret_cast<const float4*>(emb) +
                            (size_t)tok * (EMB / 4) + part * 16;
        float* drow = xs + r * 260;
#pragma unroll
        for (int i = 0; i < 16; ++i) {
            float4 v = src[i];
            int k = (part * 16 + i) * 4;
            drow[k] = v.x; drow[k + 1] = v.y; drow[k + 2] = v.z; drow[k + 3] = v.w;
        }
    }
    // transpose w_ih chunk into k-pair-major SMEM
    {
        int n = tid >> 1, half = tid & 1;
        const float4* src = reinterpret_cast<const float4*>(
            w_ih + (size_t)(n0 + n) * EMB + half * 128);
#pragma unroll
        for (int i = 0; i < 32; ++i) {
            float4 v = src[i];
            int kp = half * 64 + i * 2;
            float* d0 = ws + (kp * 129 + n) * 2;
            d0[0] = v.x; d0[1] = v.y;
            float* d1 = ws + ((kp + 1) * 129 + n) * 2;
            d1[0] = v.z; d1[1] = v.w;
        }
    }
    __syncthreads();

    const int tn = tid & 15, ts = tid >> 4;  // micro: 4 s (ts+16i) x 8 n (tn+16j)
    unsigned long long acc[4][8];
#pragma unroll
    for (int i = 0; i < 4; ++i)
#pragma unroll
        for (int j = 0; j < 8; ++j) acc[i][j] = 0ull;

    const float* xbase = xs + ts * 260;
#pragma unroll 2
    for (int kp = 0; kp < 128; ++kp) {
        unsigned long long a[4], w[8];
#pragma unroll
        for (int i = 0; i < 4; ++i)
            a[i] = *reinterpret_cast<const unsigned long long*>(xbase + i * 16 * 260 + 2 * kp);
#pragma unroll
        for (int j = 0; j < 8; ++j)
            w[j] = *reinterpret_cast<const unsigned long long*>(ws + (kp * 129 + j * 16 + tn) * 2);
#pragma unroll
        for (int i = 0; i < 4; ++i)
#pragma unroll
            for (int j = 0; j < 8; ++j) ffma2(acc[i][j], a[i], w[j]);
    }
#pragma unroll
    for (int i = 0; i < 4; ++i) {
        int s = s0 + ts + i * 16;
        float* orow = g_xg + ((size_t)s * BATCH + b) * G3 + n0;
#pragma unroll
        for (int j = 0; j < 8; ++j) {
            int n = j * 16 + tn;
            orow[n] = hsum2(acc[i][j]) + b_ih[n0 + n];
        }
    }
}

// ---------------- phase 2: persistent GRU recurrence ----------------------
// grid (16 hidden-slices, 8 batch-groups) = 128 CTAs, 192 threads, 1 CTA/SM.
// group g owns batches {g, g+8, ..., g+56} (round-robin over sorted lengths).
// CTA (kg,g): w_hh rows {j, j+512, j+1024 : j in [32kg, 32kg+32)} persistent
// in SMEM, k-pair-major [256 kp][97 float2]. Per-step 16-CTA epoch barrier.
#define P2_W_FLOATS (256 * 97 * 2)
#define P2_SMEM ((P2_W_FLOATS + 8 * 512 + 96 * 8) * 4)
__global__ void __launch_bounds__(192, 1)
k_gru(const float* __restrict__ w_hh, const float* __restrict__ b_hh,
      const int* __restrict__ lengths) {
    const int kg = blockIdx.x;   // 0..15 hidden slice
    const int g  = blockIdx.y;   // 0..7  batch group
    const int j0 = kg * 32;

    extern __shared__ float sm2[];
    float* wsm  = sm2;                       // [256 kp][97 float2]
    float* hsm  = sm2 + P2_W_FLOATS;         // [8][512] staged h
    float* hgsm = hsm + 8 * 512;             // [96 q][8 b] hidden-gate partials
    __shared__ int len_loc[8];

    const int tid = threadIdx.x;
    if (tid < 8) len_loc[tid] = lengths[g + 8 * tid];

    // persistent weight slice load (once)
    for (int idx = tid; idx < 96 * 256; idx += 192) {
        int q = idx >> 8, kp = idx & 255;
        int row = (q / 32) * HID + j0 + (q % 32);  // gate block r/z/n + unit
        float2 v = *reinterpret_cast<const float2*>(w_hh + (size_t)row * HID + 2 * kp);
        float* d = wsm + (kp * 97 + q) * 2;
        d[0] = v.x; d[1] = v.y;
    }
    __syncthreads();

    int nsteps = 0;
#pragma unroll
    for (int i = 0; i < 8; ++i) nsteps = max(nsteps, len_loc[i]);

    const int q  = tid % 96;   // gate-row within slice (warps uniform in bh)
    const int bh = tid / 96;   // batch half: 0 -> b_loc 0..3, 1 -> 4..7
    const float* wq = wsm + q * 2;

    for (int t = 0; t < nsteps; ++t) {
        const float* hr = g_h[t & 1];
        float*       hw = g_h[(t + 1) & 1];

        // stage h for all 8 local batches (values for frozen b are propagated)
        for (int idx = tid; idx < 2048; idx += 192) {
            int bl = idx >> 8, kp = idx & 255;
            float2 v = *reinterpret_cast<const float2*>(
                hr + (size_t)(g + 8 * bl) * HID + 2 * kp);
            *reinterpret_cast<float2*>(hsm + bl * 512 + 2 * kp) = v;
        }

        // prefetch this step's xg into registers (hide DRAM latency under GEMM)
        float xpre[2][3];
#pragma unroll
        for (int it = 0; it < 2; ++it) {
            int idx = tid + it * 192;
            if (idx < 256) {
                int bl = idx >> 5, jl = idx & 31;
                if (t < len_loc[bl]) {
                    const float* xg = g_xg + ((size_t)t * BATCH + (g + 8 * bl)) * G3 + j0 + jl;
                    xpre[it][0] = xg[0];
                    xpre[it][1] = xg[512];
                    xpre[it][2] = xg[1024];
                }
            }
        }
        __syncthreads();  // hsm staged

        // hg[q][b] = h[b] . w_hh_row(q)   (skip batch-half if all frozen)
        unsigned long long acc[4] = {0ull, 0ull, 0ull, 0ull};
        bool any_active = (t < len_loc[bh * 4]) || (t < len_loc[bh * 4 + 1]) ||
                          (t < len_loc[bh * 4 + 2]) || (t < len_loc[bh * 4 + 3]);
        if (any_active) {
            const float* hb = hsm + bh * 4 * 512;
#pragma unroll 8
            for (int kp = 0; kp < 256; ++kp) {
                unsigned long long w2 =
                    *reinterpret_cast<const unsigned long long*>(wq + kp * 97 * 2);
                unsigned long long h0 = *reinterpret_cast<const unsigned long long*>(hb + 2 * kp);
                unsigned long long h1 = *reinterpret_cast<const unsigned long long*>(hb + 512 + 2 * kp);
                unsigned long long h2 = *reinterpret_cast<const unsigned long long*>(hb + 1024 + 2 * kp);
                unsigned long long h3 = *reinterpret_cast<const unsigned long long*>(hb + 1536 + 2 * kp);
                ffma2(acc[0], w2, h0);
                ffma2(acc[1], w2, h1);
                ffma2(acc[2], w2, h2);
                ffma2(acc[3], w2, h3);
            }
        }
        {
            float* hgq = hgsm + q * 8 + bh * 4;
#pragma unroll
            for (int i = 0; i < 4; ++i) hgq[i] = hsum2(acc[i]);
        }
        __syncthreads();  // hgsm ready

        // pointwise GRU update + packed-sequence freeze, write next buffer
#pragma unroll
        for (int it = 0; it < 2; ++it) {
            int idx = tid + it * 192;
            if (idx < 256) {
                int bl = idx >> 5, jl = idx & 31;
                int bg = g + 8 * bl;
                float hold = hsm[bl * 512 + j0 + jl];
                float hnew = hold;
                if (t < len_loc[bl]) {
                    float gr = hgsm[jl * 8 + bl]        + b_hh[j0 + jl]         + xpre[it][0];
                    float gz = hgsm[(32 + jl) * 8 + bl] + b_hh[512 + j0 + jl]   + xpre[it][1];
                    float gh = hgsm[(64 + jl) * 8 + bl] + b_hh[1024 + j0 + jl];
                    float r = 1.0f / (1.0f + __expf(-gr));
                    float z = 1.0f / (1.0f + __expf(-gz));
                    float n = tanhf(xpre[it][2] + r * gh);
                    hnew = (1.0f - z) * n + z * hold;
                }
                hw[(size_t)bg * HID + j0 + jl] = hnew;
            }
        }

        // 16-CTA group barrier (monotonic epoch; no counter reset races)
        __threadfence();
        __syncthreads();
        if (tid == 0) {
            int arr = atomicAdd(&g_bar_cnt[g], 1) + 1;
            if (arr == 16 * (t + 1)) {
                __threadfence();
                g_bar_epoch[g] = t + 1;
            } else {
                while (g_bar_epoch[g] < t + 1) { __nanosleep(32); }
            }
            __threadfence();
        }
        __syncthreads();
    }

    // publish final hidden slice
    const float* hf = g_h[nsteps & 1];
    for (int idx = tid; idx < 256; idx += 192) {
        int bl = idx >> 5, jl = idx & 31;
        int bg = g + 8 * bl;
        g_hfinal[(size_t)bg * HID + j0 + jl] = hf[(size_t)bg * HID + j0 + jl];
    }
}

// ---------------- phase 3: logits + log_softmax ---------------------------
__global__ void __launch_bounds__(320, 1)
k_out(const float* __restrict__ w_out, const float* __restrict__ b_out,
      float* __restrict__ out) {
    __shared__ float lg[BATCH * NOUT];
    int tid = threadIdx.x;
    int b = tid / NOUT, o = tid % NOUT;
    const float* h = g_hfinal + b * HID;
    const float* w = w_out + o * HID;
    float a0 = 0.f, a1 = 0.f, a2 = 0.f, a3 = 0.f;
#pragma unroll 4
    for (int k = 0; k < HID; k += 4) {
        a0 += h[k] * w[k];
        a1 += h[k + 1] * w[k + 1];
        a2 += h[k + 2] * w[k + 2];
        a3 += h[k + 3] * w[k + 3];
    }
    lg[tid] = a0 + a1 + a2 + a3 + b_out[o];
    __syncthreads();
    if (tid < BATCH) {
        float m = lg[tid * NOUT];
#pragma unroll
        for (int i = 1; i < NOUT; ++i) m = fmaxf(m, lg[tid * NOUT + i]);
        float s = 0.f;
#pragma unroll
        for (int i = 0; i < NOUT; ++i) s += __expf(lg[tid * NOUT + i] - m);
        float lse = m + logf(s);
#pragma unroll
        for (int i = 0; i < NOUT; ++i) out[tid * NOUT + i] = lg[tid * NOUT + i] - lse;
    }
}

// ---------------- launch ---------------------------------------------------
extern "C" void kernel_launch(void* const* d_in, const int* in_sizes, int n_in,
                              void* d_out, int out_size) {
    const int*   seq     = (const int*)d_in[0];
    const int*   lengths = (const int*)d_in[1];
    const float* emb     = (const float*)d_in[2];
    const float* w_ih    = (const float*)d_in[3];
    const float* w_hh    = (const float*)d_in[4];
    const float* b_ih    = (const float*)d_in[5];
    const float* b_hh    = (const float*)d_in[6];
    const float* w_out   = (const float*)d_in[7];
    const float* b_out   = (const float*)d_in[8];
    float*       out     = (float*)d_out;

    cudaFuncSetAttribute(k_xgates, cudaFuncAttributeMaxDynamicSharedMemorySize, P1_SMEM);
    cudaFuncSetAttribute(k_gru,    cudaFuncAttributeMaxDynamicSharedMemorySize, P2_SMEM);

    k_init<<<128, 256>>>();
    k_xgates<<<dim3(BATCH, SEQ / 64, G3 / 128), 256, P1_SMEM>>>(seq, lengths, emb, w_ih, b_ih);
    k_gru<<<dim3(16, 8), 192, P2_SMEM>>>(w_hh, b_hh, lengths);
    k_out<<<1, 320>>>(w_out, b_out, out);
}

// round 9
// speedup vs baseline: 1.3946x; 1.3946x over previous
#include <cuda_runtime.h>
#include <cstdint>

#define VOCAB 32000
#define EMB   256
#define HID   512
#define NOUT  5
#define SEQ   512
#define BATCH 64
#define G3    1536   // 3*HID

// ---------------- scratch (static device allocations only) ----------------
__device__ float g_xg[(size_t)SEQ * BATCH * G3];   // 201 MB: precomputed input gates
__device__ float g_h[2][BATCH * HID];              // double-buffered hidden state
__device__ float g_hfinal[BATCH * HID];            // final hidden per batch
__device__ int            g_bar_cnt[8];            // per-group arrival counter (monotonic)
__device__ volatile int   g_bar_epoch[8];          // per-group release epoch

// ---------------- packed fp32x2 FMA (Blackwell; 2x FFMA throughput) -------
__device__ __forceinline__ void ffma2(unsigned long long& acc,
                                      unsigned long long a,
                                      unsigned long long b) {
    asm("fma.rn.f32x2 %0, %1, %2, %0;" : "+l"(acc) : "l"(a), "l"(b));
}
__device__ __forceinline__ float hsum2(unsigned long long v) {
    float lo = __uint_as_float((unsigned)(v & 0xffffffffull));
    float hi = __uint_as_float((unsigned)(v >> 32));
    return lo + hi;
}

// ---------------- init: zero h0 + barrier state (every launch) ------------
__global__ void k_init() {
    int i = blockIdx.x * blockDim.x + threadIdx.x;
    if (i < BATCH * HID) g_h[0][i] = 0.0f;
    if (i < 8) { g_bar_cnt[i] = 0; g_bar_epoch[i] = 0; }
}

// ---------------- phase 1: x_gates = emb[seq] @ w_ih^T + b_ih -------------
// grid (64 batch, 8 s-tiles of 64, 12 n-chunks of 128), 256 threads.
#define P1_SMEM ((64 * 260 + 128 * 258) * 4)
__global__ void __launch_bounds__(256, 1)
k_xgates(const int* __restrict__ seq, const int* __restrict__ lengths,
         const float* __restrict__ emb, const float* __restrict__ w_ih,
         const float* __restrict__ b_ih) {
    const int b = blockIdx.x, st = blockIdx.y, nc = blockIdx.z;
    const int s0 = st * 64, n0 = nc * 128;
    if (s0 >= lengths[b]) return;  // dead steps never read downstream

    extern __shared__ float sm1[];
    float* xs = sm1;               // [64][260]
    float* ws = sm1 + 64 * 260;    // [128][258] = [kp][129 float2]
    const int tid = threadIdx.x;

    // gather 64 embedding rows (one s-tile, fixed batch)
    {
        int r = tid >> 2, part = tid & 3;
        int tok = seq[(s0 + r) * BATCH + b];
        const float4* src = reinterpret_cast<const float4*>(emb) +
                            (size_t)tok * (EMB / 4) + part * 16;
        float* drow = xs + r * 260;
#pragma unroll
        for (int i = 0; i < 16; ++i) {
            float4 v = src[i];
            int k = (part * 16 + i) * 4;
            drow[k] = v.x; drow[k + 1] = v.y; drow[k + 2] = v.z; drow[k + 3] = v.w;
        }
    }
    // transpose w_ih chunk into k-pair-major SMEM
    {
        int n = tid >> 1, half = tid & 1;
        const float4* src = reinterpret_cast<const float4*>(
            w_ih + (size_t)(n0 + n) * EMB + half * 128);
#pragma unroll
        for (int i = 0; i < 32; ++i) {
            float4 v = src[i];
            int kp = half * 64 + i * 2;
            float* d0 = ws + (kp * 129 + n) * 2;
            d0[0] = v.x; d0[1] = v.y;
            float* d1 = ws + ((kp + 1) * 129 + n) * 2;
            d1[0] = v.z; d1[1] = v.w;
        }
    }
    __syncthreads();

    const int tn = tid & 15, ts = tid >> 4;  // micro: 4 s (ts+16i) x 8 n (tn+16j)
    unsigned long long acc[4][8];
#pragma unroll
    for (int i = 0; i < 4; ++i)
#pragma unroll
        for (int j = 0; j < 8; ++j) acc[i][j] = 0ull;

    const float* xbase = xs + ts * 260;
#pragma unroll 2
    for (int kp = 0; kp < 128; ++kp) {
        unsigned long long a[4], w[8];
#pragma unroll
        for (int i = 0; i < 4; ++i)
            a[i] = *reinterpret_cast<const unsigned long long*>(xbase + i * 16 * 260 + 2 * kp);
#pragma unroll
        for (int j = 0; j < 8; ++j)
            w[j] = *reinterpret_cast<const unsigned long long*>(ws + (kp * 129 + j * 16 + tn) * 2);
#pragma unroll
        for (int i = 0; i < 4; ++i)
#pragma unroll
            for (int j = 0; j < 8; ++j) ffma2(acc[i][j], a[i], w[j]);
    }
#pragma unroll
    for (int i = 0; i < 4; ++i) {
        int s = s0 + ts + i * 16;
        float* orow = g_xg + ((size_t)s * BATCH + b) * G3 + n0;
#pragma unroll
        for (int j = 0; j < 8; ++j) {
            int n = j * 16 + tn;
            orow[n] = hsum2(acc[i][j]) + b_ih[n0 + n];
        }
    }
}

// ---------------- phase 2: persistent GRU recurrence ----------------------
// grid (16 hidden-slices, 8 batch-groups) = 128 CTAs, 384 threads, 1 CTA/SM.
// group g owns batches {g, g+8, ..., g+56} (round-robin over sorted lengths,
// so lengths are DESCENDING in local index bl).
// Weights persistent in SMEM as [kp2][q] float4 for LDS.128 GEMM.
// Thread = (kh 0..1 K-half, bh 0..1 batch-half, q 0..95 gate-row).
#define P2_W_F4   (128 * 96)
#define P2_SMEM   ((P2_W_F4 * 4 + 8 * 512 + 2 * 8 * 96) * 4)
__global__ void __launch_bounds__(384, 1)
k_gru(const float* __restrict__ w_hh, const float* __restrict__ b_hh,
      const int* __restrict__ lengths) {
    const int kg = blockIdx.x;   // 0..15 hidden slice
    const int g  = blockIdx.y;   // 0..7  batch group
    const int j0 = kg * 32;

    extern __shared__ float sm2[];
    float4* w4  = reinterpret_cast<float4*>(sm2);   // [128 kp2][96 q]
    float*  hsm = sm2 + P2_W_F4 * 4;                // [8 bl][512]
    float*  hgp = hsm + 8 * 512;                    // [2 kh][8 bl][96 q]
    __shared__ int len_loc[8];

    const int tid = threadIdx.x;
    const int kh  = tid / 192;          // warp-uniform
    const int rr  = tid % 192;
    const int bh  = rr / 96;            // warp-uniform
    const int q   = rr % 96;            // consecutive within warp

    if (tid < 8) len_loc[tid] = lengths[g + 8 * tid];

    // persistent weight slice load (once): w4[kp2][q] = w_hh[row(q)][4kp2..4kp2+3]
    for (int idx = tid; idx < 96 * 128; idx += 384) {
        int qq = idx >> 7, kp2 = idx & 127;
        int row = (qq / 32) * HID + j0 + (qq % 32);
        w4[kp2 * 96 + qq] =
            *(reinterpret_cast<const float4*>(w_hh + (size_t)row * HID) + kp2);
    }
    __syncthreads();

    const int nsteps = len_loc[0];      // lengths descending in bl

    // ---- pointwise thread state (tid < 256 handles one (bl, jl)) ----
    const bool pw = (tid < 256);
    const int bl = tid >> 5, jl = tid & 31;
    const int bg = g + 8 * bl;
    int mylen = 0;
    float bhr = 0.f, bhz = 0.f, bhn = 0.f;
    const float* xp = nullptr;
    size_t hoff = 0;
    float hcur = 0.f;                   // this thread's h element, lives in a reg
    if (pw) {
        mylen = len_loc[bl];
        bhr = b_hh[j0 + jl];
        bhz = b_hh[HID + j0 + jl];
        bhn = b_hh[2 * HID + j0 + jl];
        xp  = g_xg + (size_t)bg * G3 + j0 + jl;
        hoff = (size_t)bg * HID + j0 + jl;
    }

    const ulonglong2* wp0 =
        reinterpret_cast<const ulonglong2*>(w4 + (size_t)kh * 64 * 96 + q);
    const ulonglong2* hp0 =
        reinterpret_cast<const ulonglong2*>(hsm) + (size_t)bh * 4 * 128 + kh * 64;

    for (int t = 0; t < nsteps; ++t) {
        const float* hr = g_h[t & 1];
        float*       hw = g_h[(t + 1) & 1];

        // prefetch this step's xg (DRAM) -- overlaps staging + GEMM
        float x0 = 0.f, x1 = 0.f, x2 = 0.f;
        const bool act = pw && (t < mylen);
        if (act) {
            x0 = __ldcs(xp);
            x1 = __ldcs(xp + HID);
            x2 = __ldcs(xp + 2 * HID);
        }

        // active count: lengths desc in bl => active set is prefix [0, A)
        int A = 0;
#pragma unroll
        for (int i = 0; i < 8; ++i) A += (t < len_loc[i]) ? 1 : 0;

        // stage h of active batches (L2-coherent; frozen h never read)
        for (int idx = tid; idx < A * 128; idx += 384) {
            int bb = idx >> 7, k4 = idx & 127;
            float4 v = __ldcg(
                reinterpret_cast<const float4*>(hr + (size_t)(g + 8 * bb) * HID) + k4);
            reinterpret_cast<float4*>(hsm)[bb * 128 + k4] = v;
        }
        __syncthreads();

        // ---- GEMM: hg[q][b] = h[b] . w_hh_row(q), LDS.128 + f32x2 FMA ----
        unsigned long long aL0 = 0, aH0 = 0, aL1 = 0, aH1 = 0;
        unsigned long long aL2 = 0, aH2 = 0, aL3 = 0, aH3 = 0;
        const bool pairA = t < len_loc[bh * 4];       // batches {0,1} of half
        const bool pairB = t < len_loc[bh * 4 + 2];   // batches {2,3} of half
        const ulonglong2* wp = wp0;
        const ulonglong2* hp = hp0;
        if (pairB) {  // all 4 batches of this half
#pragma unroll 8
            for (int i = 0; i < 64; ++i) {
                ulonglong2 w = *wp; wp += 96;
                ulonglong2 h0 = hp[0], h1 = hp[128], h2 = hp[256], h3 = hp[384];
                ++hp;
                ffma2(aL0, w.x, h0.x); ffma2(aH0, w.y, h0.y);
                ffma2(aL1, w.x, h1.x); ffma2(aH1, w.y, h1.y);
                ffma2(aL2, w.x, h2.x); ffma2(aH2, w.y, h2.y);
                ffma2(aL3, w.x, h3.x); ffma2(aH3, w.y, h3.y);
            }
        } else if (pairA) {  // only batches {0,1} still active
#pragma unroll 8
            for (int i = 0; i < 64; ++i) {
                ulonglong2 w = *wp; wp += 96;
                ulonglong2 h0 = hp[0], h1 = hp[128];
                ++hp;
                ffma2(aL0, w.x, h0.x); ffma2(aH0, w.y, h0.y);
                ffma2(aL1, w.x, h1.x); ffma2(aH1, w.y, h1.y);
            }
        }
        {
            float* o = hgp + kh * 768 + bh * 4 * 96 + q;
            o[0]   = hsum2(aL0) + hsum2(aH0);
            o[96]  = hsum2(aL1) + hsum2(aH1);
            o[192] = hsum2(aL2) + hsum2(aH2);
            o[288] = hsum2(aL3) + hsum2(aH3);
        }
        __syncthreads();

        // ---- pointwise GRU update (h element lives in hcur register) ----
        if (act) {
            const float* hgb = hgp + bl * 96 + jl;
            float gr  = hgb[0]  + hgb[768] + bhr + x0;
            float gz  = hgb[32] + hgb[800] + bhz + x1;
            float gnh = hgb[64] + hgb[832] + bhn;
            float r = 1.0f / (1.0f + __expf(-gr));
            float z = 1.0f / (1.0f + __expf(-gz));
            float n = tanhf(x2 + r * gnh);
            hcur = (1.0f - z) * n + z * hcur;
            hw[hoff] = hcur;   // frozen batches never stored (never read either)
        }

        // ---- 16-CTA group barrier (monotonic epoch) ----
        __threadfence();
        __syncthreads();
        if (tid == 0) {
            int arr = atomicAdd(&g_bar_cnt[g], 1) + 1;
            if (arr == 16 * (t + 1)) {
                __threadfence();
                g_bar_epoch[g] = t + 1;
            } else {
                while (g_bar_epoch[g] < t + 1) { __nanosleep(20); }
            }
        }
        __syncthreads();

        if (pw) xp += (size_t)BATCH * G3;
    }

    // publish final hidden straight from registers
    if (pw) g_hfinal[hoff] = hcur;
}

// ---------------- phase 3: logits + log_softmax (warp per logit) ----------
__global__ void __launch_bounds__(160, 1)
k_out(const float* __restrict__ w_out, const float* __restrict__ b_out,
      float* __restrict__ out) {
    const int b = blockIdx.x;
    const int o = threadIdx.x >> 5, lane = threadIdx.x & 31;
    const float4* h4 = reinterpret_cast<const float4*>(g_hfinal + (size_t)b * HID);
    const float4* w4 = reinterpret_cast<const float4*>(w_out + (size_t)o * HID);
    float s = 0.f;
#pragma unroll
    for (int i = 0; i < 4; ++i) {
        float4 hv = h4[lane + 32 * i];
        float4 wv = w4[lane + 32 * i];
        s += hv.x * wv.x + hv.y * wv.y + hv.z * wv.z + hv.w * wv.w;
    }
#pragma unroll
    for (int d = 16; d; d >>= 1) s += __shfl_down_sync(0xffffffffu, s, d);
    __shared__ float lg[NOUT];
    if (lane == 0) lg[o] = s + b_out[o];
    __syncthreads();
    if (threadIdx.x == 0) {
        float m = lg[0];
#pragma unroll
        for (int i = 1; i < NOUT; ++i) m = fmaxf(m, lg[i]);
        float sum = 0.f;
#pragma unroll
        for (int i = 0; i < NOUT; ++i) sum += __expf(lg[i] - m);
        float lse = m + logf(sum);
#pragma unroll
        for (int i = 0; i < NOUT; ++i) out[b * NOUT + i] = lg[i] - lse;
    }
}

// ---------------- launch ---------------------------------------------------
extern "C" void kernel_launch(void* const* d_in, const int* in_sizes, int n_in,
                              void* d_out, int out_size) {
    const int*   seq     = (const int*)d_in[0];
    const int*   lengths = (const int*)d_in[1];
    const float* emb     = (const float*)d_in[2];
    const float* w_ih    = (const float*)d_in[3];
    const float* w_hh    = (const float*)d_in[4];
    const float* b_ih    = (const float*)d_in[5];
    const float* b_hh    = (const float*)d_in[6];
    const float* w_out   = (const float*)d_in[7];
    const float* b_out   = (const float*)d_in[8];
    float*       out     = (float*)d_out;

    cudaFuncSetAttribute(k_xgates, cudaFuncAttributeMaxDynamicSharedMemorySize, P1_SMEM);
    cudaFuncSetAttribute(k_gru,    cudaFuncAttributeMaxDynamicSharedMemorySize, P2_SMEM);

    k_init<<<128, 256>>>();
    k_xgates<<<dim3(BATCH, SEQ / 64, G3 / 128), 256, P1_SMEM>>>(seq, lengths, emb, w_ih, b_ih);
    k_gru<<<dim3(16, 8), 384, P2_SMEM>>>(w_hh, b_hh, lengths);
    k_out<<<BATCH, 160>>>(w_out, b_out, out);
}